// round 13
// baseline (speedup 1.0000x reference)
#include <cuda_runtime.h>
#include <cuda_bf16.h>

// AngularSymmetryMod: out[b,i,p] = 0.125 * sum_{j,k} (1 + lambda_p*cos(theta_ijk - th_p))^4
//                                   * exp(-1.12*((Rij+Rik)/2 - Rs_p)^2) * f_ij * f_ik
// p = lambda*20 + Rs*4 + th (np.meshgrid 'xy'). One block per (b,i); j<=k pairs, wt 2 off-diag.
// cos literal: cosf(fl32(theta - th)) bit-matches reference rounding at large theta.
// Radial factorization (exact algebra): exp(-1.12(avg-Rs)^2) = A_r[j]*B_r[k]*exp(-0.56 Rj Rk),
//   A_r[a] = exp(-0.28 Ra^2 + 1.12 Rs_r Ra),  B_r[a] = A_r[a]*exp(-1.12 Rs_r^2); F folded in.
//
// R11 evidence: 38.8% issue, dur flat despite -40% inst => per-warp chain-bound (~9 cyc/issue).
// R12/R13: explicit dual-pair interleave (front chains then alternated cosf chains),
//          parallelized prologue (table builds strided over all 128 threads).

#define TPB 128
#define NATOM 32
#define NPAIR (NATOM * (NATOM + 1) / 2)   // 528

typedef unsigned long long u64;

__device__ __forceinline__ u64 pack2(float lo, float hi) {
    u64 r; asm("mov.b64 %0, {%1, %2};" : "=l"(r) : "f"(lo), "f"(hi)); return r;
}
__device__ __forceinline__ void unpack2(u64 v, float& lo, float& hi) {
    asm("mov.b64 {%0, %1}, %2;" : "=f"(lo), "=f"(hi) : "l"(v));
}
__device__ __forceinline__ u64 mul2(u64 a, u64 b) {
    u64 r; asm("mul.rn.f32x2 %0, %1, %2;" : "=l"(r) : "l"(a), "l"(b)); return r;
}
__device__ __forceinline__ u64 fma2(u64 a, u64 b, u64 c) {
    u64 r; asm("fma.rn.f32x2 %0, %1, %2, %3;" : "=l"(r) : "l"(a), "l"(b), "l"(c)); return r;
}

__global__ __launch_bounds__(TPB, 4)
void angsym_kernel(const float* __restrict__ dcut,
                   const float* __restrict__ dmat,
                   const float* __restrict__ coords,
                   float* __restrict__ out)
{
    const int bi = blockIdx.x;             // 0..511
    const int b = bi >> 5;
    const int i = bi & 31;

    __shared__ float4 atomv[NATOM];            // (vx, vy, vz, R)
    __shared__ float  Fsh[NATOM];
    __shared__ float  Ash[NATOM][5];           // F * exp(-0.28 R^2 + 1.12 Rs_r R)
    __shared__ float  Bsh[NATOM][5];           // A * exp(-1.12 Rs_r^2) * F
    __shared__ unsigned short jk[NPAIR];
    __shared__ float  red[40][TPB];            // 20 KB transpose-reduce

    const int t = threadIdx.x;

    const float Rs[5] = {
        (float)(0.5  / 0.52917721092),
        (float)(1.17 / 0.52917721092),
        (float)(1.83 / 0.52917721092),
        (float)(2.5  / 0.52917721092),
        (float)(3.17 / 0.52917721092)
    };
    const float TH[4] = { 0.0f, 1.57f, 3.14f, 4.71f };

    // phase 1: per-atom loads (warp 0)
    if (t < NATOM) {
        const int j = t;
        const float cix = coords[(b * NATOM + i) * 3 + 0];
        const float ciy = coords[(b * NATOM + i) * 3 + 1];
        const float ciz = coords[(b * NATOM + i) * 3 + 2];
        atomv[j] = make_float4(cix - coords[(b * NATOM + j) * 3 + 0],
                               ciy - coords[(b * NATOM + j) * 3 + 1],
                               ciz - coords[(b * NATOM + j) * 3 + 2],
                               dmat[(b * NATOM + i) * NATOM + j]);
        Fsh[j] = dcut[(b * NATOM + i) * NATOM + j];
    }
    __syncthreads();

    // phase 2: tables, strided over ALL threads (was serialized on warp 0 in R11)
#pragma unroll
    for (int idx = t; idx < NATOM * 5; idx += TPB) {
        const int a = idx & 31;
        const int r = idx >> 5;
        const float R = atomv[a].w;
        const float F = Fsh[a];
        const float A = __expf(fmaf(1.12f * Rs[r], R, -0.28f * R * R));
        Ash[a][r] = A * F;
        Bsh[a][r] = A * __expf(-1.12f * Rs[r] * Rs[r]) * F;
    }
    for (int p = t; p < NPAIR; p += TPB) {
        int k = (int)((sqrtf(8.0f * (float)p + 1.0f) - 1.0f) * 0.5f);
        if ((k + 1) * (k + 2) / 2 <= p) ++k;
        if (k * (k + 1) / 2 > p) --k;
        const int j = p - k * (k + 1) / 2;
        jk[p] = (unsigned short)(j | (k << 8));
    }
    __syncthreads();

    // acc2[r*4+tt] packs (lambda=+1 -> out r*4+tt, lambda=-1 -> out 20+r*4+tt)
    u64 acc2[20];
#pragma unroll
    for (int p = 0; p < 20; ++p) acc2[p] = 0ull;

    // front-end: loads + dot + div + radial (long-latency chains)
    auto front = [&](int p, float& theta, u64 (&rv2)[5]) {
        const unsigned int e = jk[p];
        const int j = e & 31;
        const int k = e >> 8;
        const float4 aj = atomv[j];
        const float4 ak = atomv[k];
        const float dot = aj.x * ak.x + aj.y * ak.y + aj.z * ak.z;
        const float RR  = aj.w * ak.w;
        theta = dot / (RR + 1e-5f);                       // IEEE div (bit-safe)
        const float X = __expf(-0.56f * RR) * ((j != k) ? 2.0f : 1.0f);
#pragma unroll
        for (int r = 0; r < 5; ++r) {
            const float rv = Ash[j][r] * Bsh[k][r] * X;
            rv2[r] = pack2(rv, rv);
        }
    };

#pragma unroll
    for (int batch = 0; batch < 2; ++batch) {
        float th0, th1;
        u64 rv0[5], rv1[5];
        front(t + batch * 256,       th0, rv0);
        front(t + batch * 256 + 128, th1, rv1);
        // back-end: cosf chains of the two pairs alternated for ILP
#pragma unroll
        for (int tt = 0; tt < 4; ++tt) {
            const float ca0 = cosf(th0 - TH[tt]);
            const float ca1 = cosf(th1 - TH[tt]);
            const u64 pa0 = pack2(1.0f + ca0, 1.0f - ca0);
            const u64 pa1 = pack2(1.0f + ca1, 1.0f - ca1);
            const u64 q0 = mul2(pa0, pa0);
            const u64 q1 = mul2(pa1, pa1);
            const u64 p40 = mul2(q0, q0);
            const u64 p41 = mul2(q1, q1);
#pragma unroll
            for (int r = 0; r < 5; ++r) {
                acc2[r * 4 + tt] = fma2(p40, rv0[r], acc2[r * 4 + tt]);
                acc2[r * 4 + tt] = fma2(p41, rv1[r], acc2[r * 4 + tt]);
            }
        }
    }
    if (t < 16) {
        float th;
        u64 rv[5];
        front(512 + t, th, rv);
#pragma unroll
        for (int tt = 0; tt < 4; ++tt) {
            const float ca = cosf(th - TH[tt]);
            const u64 pa = pack2(1.0f + ca, 1.0f - ca);
            const u64 q  = mul2(pa, pa);
            const u64 p4 = mul2(q, q);
#pragma unroll
            for (int r = 0; r < 5; ++r)
                acc2[r * 4 + tt] = fma2(p4, rv[r], acc2[r * 4 + tt]);
        }
    }

    __syncthreads();
#pragma unroll
    for (int p = 0; p < 20; ++p) {
        float lo, hi;
        unpack2(acc2[p], lo, hi);
        red[p][t]      = lo;
        red[20 + p][t] = hi;
    }
    __syncthreads();

    // 4 warps x 10 outputs each
    const int warp = t >> 5, lane = t & 31;
#pragma unroll
    for (int q = 0; q < 10; ++q) {
        const int p = warp * 10 + q;
        float v = red[p][lane] + red[p][lane + 32] + red[p][lane + 64] + red[p][lane + 96];
        v += __shfl_down_sync(0xffffffffu, v, 16);
        v += __shfl_down_sync(0xffffffffu, v, 8);
        v += __shfl_down_sync(0xffffffffu, v, 4);
        v += __shfl_down_sync(0xffffffffu, v, 2);
        v += __shfl_down_sync(0xffffffffu, v, 1);
        if (lane == 0) out[bi * 40 + p] = 0.125f * v;    // 2^{1-zeta} = 0.125
    }
}

extern "C" void kernel_launch(void* const* d_in, const int* in_sizes, int n_in,
                              void* d_out, int out_size)
{
    const float* dcut   = (const float*)d_in[0];  // d_cutoff (16,32,32)
    const float* dmat   = (const float*)d_in[1];  // d        (16,32,32)
    const float* coords = (const float*)d_in[2];  // atom_coordinates (16,32,3)
    float* out = (float*)d_out;                   // (16,32,40)
    (void)in_sizes; (void)n_in; (void)out_size;

    angsym_kernel<<<512, TPB>>>(dcut, dmat, coords, out);
}